// round 1
// baseline (speedup 1.0000x reference)
#include <cuda_runtime.h>

// Problem constants (fixed by dataset shapes)
#define KK 20           // classes
#define CC 96           // feature channels
#define TILE_P 16       // points staged per tile
#define NG 4            // point groups per block
#define GROUP 48        // threads per group: 4 kt * 12 ct
#define NTHREADS (NG * GROUP)   // 192
#define K_T 5           // k's per thread (4 kt * 5 = 20)
#define C_T 8           // channels per thread (12 ct * 8 = 96)
#define MAX_B 64

// scratch (no allocations allowed)
__device__ float g_denom[MAX_B * KK];
__device__ int   g_off[MAX_B + 1];

// ---------------------------------------------------------------------------
// Kernel 0: zero output + denom scratch, compute segment offsets (binary search
// on sorted batch_indices; thread b finds lower_bound(b), thread B gets N).
// ---------------------------------------------------------------------------
__global__ void setup_kernel(const int* __restrict__ bidx, int N, int B,
                             float* __restrict__ out, int out_size) {
    int tid = blockIdx.x * blockDim.x + threadIdx.x;
    for (int i = tid; i < out_size; i += gridDim.x * blockDim.x) out[i] = 0.0f;
    if (blockIdx.x == 0) {
        for (int i = threadIdx.x; i < MAX_B * KK; i += blockDim.x) g_denom[i] = 0.0f;
        if ((int)threadIdx.x <= B) {
            int b = threadIdx.x;
            int lo = 0, hi = N;
            while (lo < hi) {
                int mid = (lo + hi) >> 1;
                if (bidx[mid] < b) lo = mid + 1; else hi = mid;
            }
            g_off[b] = lo;
        }
    }
}

// ---------------------------------------------------------------------------
// Kernel 1: main fused pass.
// Accumulates out[b,k,c] += exp(probs[n,k]) * feats[n,c]  and
//            g_denom[b,k] += exp(probs[n,k])   over each block's point range.
// ---------------------------------------------------------------------------
__global__ void __launch_bounds__(NTHREADS)
gather_kernel(const float* __restrict__ feats,
              const float* __restrict__ probs,
              float* __restrict__ out,
              int splits) {
    __shared__ float4 sh_f[TILE_P][CC / 4];     // staged feature tile (6144 B)
    __shared__ float  sh_e[TILE_P][KK];         // staged exp(probs) (1280 B)
    __shared__ float  sh_red[KK * CC];          // cross-group reduction (7680 B)
    __shared__ float  sh_d[NG][KK];             // denom partials

    const int b = blockIdx.x / splits;
    const int s = blockIdx.x % splits;
    const int seg0 = g_off[b];
    const int seg1 = g_off[b + 1];
    const int len  = seg1 - seg0;
    const int r0 = seg0 + (int)((long long)len * s / splits);
    const int r1 = seg0 + (int)((long long)len * (s + 1) / splits);

    const int tid = threadIdx.x;
    const int g   = tid / GROUP;        // 0..3 point group
    const int gt  = tid % GROUP;
    const int kt  = gt / 12;            // 0..3
    const int ct  = gt % 12;            // 0..11

    float acc[K_T][C_T];
#pragma unroll
    for (int j = 0; j < K_T; j++)
#pragma unroll
        for (int q = 0; q < C_T; q++) acc[j][q] = 0.0f;
    float dacc[K_T];
#pragma unroll
    for (int j = 0; j < K_T; j++) dacc[j] = 0.0f;

    for (int base = r0; base < r1; base += TILE_P) {
        __syncthreads();
        // stage feats tile: 384 float4, 2 per thread, coalesced
#pragma unroll
        for (int j = 0; j < 2; j++) {
            int v = tid + j * NTHREADS;            // 0..383
            int p  = v / (CC / 4);
            int c4 = v % (CC / 4);
            int idx = base + p;
            float4 val = make_float4(0.f, 0.f, 0.f, 0.f);
            if (idx < r1)
                val = reinterpret_cast<const float4*>(feats)[idx * (CC / 4) + c4];
            sh_f[p][c4] = val;
        }
        // stage exp(probs) tile: 320 floats
#pragma unroll
        for (int j = 0; j < 2; j++) {
            int v = tid + j * NTHREADS;
            if (v < TILE_P * KK) {
                int p = v / KK, k = v % KK;
                int idx = base + p;
                float e = 0.0f;
                if (idx < r1) e = __expf(probs[idx * KK + k]);
                sh_e[p][k] = e;
            }
        }
        __syncthreads();

        // rank-TILE_P update; each group takes every NG-th point
#pragma unroll
        for (int p = 0; p < TILE_P / NG; p++) {
            const int pp = p * NG + g;
            float4 fA = sh_f[pp][ct * 2];
            float4 fB = sh_f[pp][ct * 2 + 1];
#pragma unroll
            for (int j = 0; j < K_T; j++) {
                float e = sh_e[pp][kt * K_T + j];
                acc[j][0] += e * fA.x;  acc[j][1] += e * fA.y;
                acc[j][2] += e * fA.z;  acc[j][3] += e * fA.w;
                acc[j][4] += e * fB.x;  acc[j][5] += e * fB.y;
                acc[j][6] += e * fB.z;  acc[j][7] += e * fB.w;
                if (ct == 0) dacc[j] += e;
            }
        }
    }

    // ---- block-level reduction across the 4 point groups ----
    __syncthreads();
    if (ct == 0) {
#pragma unroll
        for (int j = 0; j < K_T; j++) sh_d[g][kt * K_T + j] = dacc[j];
    }
    if (g == 1) {
#pragma unroll
        for (int j = 0; j < K_T; j++) {
            int k = kt * K_T + j;
#pragma unroll
            for (int q = 0; q < C_T; q++)
                sh_red[k * CC + ct * C_T + q] = acc[j][q];
        }
    }
    __syncthreads();
    if (g == 2) {
#pragma unroll
        for (int j = 0; j < K_T; j++) {
            int k = kt * K_T + j;
#pragma unroll
            for (int q = 0; q < C_T; q++)
                sh_red[k * CC + ct * C_T + q] += acc[j][q];
        }
    }
    __syncthreads();
    if (g == 3) {
#pragma unroll
        for (int j = 0; j < K_T; j++) {
            int k = kt * K_T + j;
#pragma unroll
            for (int q = 0; q < C_T; q++)
                sh_red[k * CC + ct * C_T + q] += acc[j][q];
        }
    }
    __syncthreads();
    if (g == 0) {
        float* outb = out + b * (KK * CC);
#pragma unroll
        for (int j = 0; j < K_T; j++) {
            int k = kt * K_T + j;
#pragma unroll
            for (int q = 0; q < C_T; q++) {
                float v = acc[j][q] + sh_red[k * CC + ct * C_T + q];
                atomicAdd(&outb[k * CC + ct * C_T + q], v);
            }
        }
        if (ct == 0) {
#pragma unroll
            for (int j = 0; j < K_T; j++) {
                int k = kt * K_T + j;
                float dv = dacc[j] + sh_d[1][k] + sh_d[2][k] + sh_d[3][k];
                atomicAdd(&g_denom[b * KK + k], dv);
            }
        }
    }
}

// ---------------------------------------------------------------------------
// Kernel 2: normalize out[b,k,c] /= denom[b,k] (empty segments stay 0)
// ---------------------------------------------------------------------------
__global__ void norm_kernel(float* __restrict__ out, int total) {
    int i = blockIdx.x * blockDim.x + threadIdx.x;
    if (i < total) {
        int bk = i / CC;
        float d = g_denom[bk];
        out[i] = (d > 0.0f) ? out[i] / d : 0.0f;
    }
}

// ---------------------------------------------------------------------------
extern "C" void kernel_launch(void* const* d_in, const int* in_sizes, int n_in,
                              void* d_out, int out_size) {
    const float* feats = (const float*)d_in[0];   // [N, C]
    const float* probs = (const float*)d_in[1];   // [N, K]
    const int*   bidx  = (const int*)d_in[3];     // [N], sorted
    float* out = (float*)d_out;                   // [B, K, C]

    const int N = in_sizes[3];
    const int B = out_size / (KK * CC);

    setup_kernel<<<64, 256>>>(bidx, N, B, out, out_size);

    int splits = (296 + B - 1) / B;               // ~296 blocks total
    if (splits < 1) splits = 1;
    gather_kernel<<<B * splits, NTHREADS>>>(feats, probs, out, splits);

    norm_kernel<<<(out_size + 255) / 256, 256>>>(out, out_size);
}